// round 10
// baseline (speedup 1.0000x reference)
#include <cuda_runtime.h>
#include <cuda_bf16.h>
#include <cuda_fp16.h>
#include <math.h>

// ---------------- problem constants ----------------
#define N_NODES 100000
#define N_EDGES 3200000
#define IN_F    500
#define HID     64
#define OUT_F   64
#define ALPHA   0.1f
#define K_ITERS 10

#define NSCAN_BLOCKS ((N_NODES + 1023) / 1024)   // 98
#define KK 8                                      // gemm k-tile
#define SCALE_S 0.0625                            // 1/16 per-iteration z scaling
#define WQ_SCALE 32767.0f
#define WQ_INV   (1.0f / 32767.0f)
#define EPK_CAP  (N_EDGES + 8 * N_NODES)          // padded edge capacity

typedef unsigned long long u64;

// ---------------- static device scratch ----------------
__device__ float    g_h1[N_NODES * HID];          // relu(x@W1+b1)
__device__ float    g_h [N_NODES * OUT_F];        // fp32 h (final iter)
__device__ __half   g_hh[N_NODES * OUT_F];        // fp16 h (= y_0, alpha term)
__device__ __half   g_ya[N_NODES * OUT_F];        // fp16 iterate ping
__device__ __half   g_yb[N_NODES * OUT_F];        // fp16 iterate pong
__device__ int      g_deg[N_NODES];               // ALWAYS zero at launch entry
__device__ int      g_off[N_NODES + 1];           // PADDED offsets (mult of 8)
__device__ int      g_pos[N_NODES];
__device__ unsigned g_epk[EPK_CAP];               // packed edge: w15 | src17
__device__ int      g_bsum[NSCAN_BLOCKS];

// ---------------- f32x2 helpers ----------------
__device__ __forceinline__ u64 pack2(float x, float y) {
    u64 r; asm("mov.b64 %0, {%1, %2};" : "=l"(r) : "f"(x), "f"(y)); return r;
}
__device__ __forceinline__ void unpack2(float& x, float& y, u64 v) {
    asm("mov.b64 {%0, %1}, %2;" : "=f"(x), "=f"(y) : "l"(v));
}
#define FMA2(acc, a, b) asm("fma.rn.f32x2 %0, %1, %2, %0;" : "+l"(acc) : "l"(a), "l"(b))

// ---------------- CSR construction (5 kernels, padded to 8) ----------------
__global__ void hist_kernel(const int* __restrict__ dst) {
    int i = blockIdx.x * blockDim.x + threadIdx.x;
    if (i * 4 + 3 < N_EDGES) {
        int4 d = ((const int4*)dst)[i];
        atomicAdd(&g_deg[d.x], 1);
        atomicAdd(&g_deg[d.y], 1);
        atomicAdd(&g_deg[d.z], 1);
        atomicAdd(&g_deg[d.w], 1);
    } else {
        for (int e = i * 4; e < N_EDGES; e++) atomicAdd(&g_deg[dst[e]], 1);
    }
}

__global__ void scan_local_kernel() {
    __shared__ int s[1024];
    int tid = threadIdx.x;
    int i = blockIdx.x * 1024 + tid;
    int vr = (i < N_NODES) ? g_deg[i] : 0;
    int v  = (vr + 7) & ~7;                       // padded degree
    s[tid] = v;
    __syncthreads();
    #pragma unroll
    for (int d = 1; d < 1024; d <<= 1) {
        int t = (tid >= d) ? s[tid - d] : 0;
        __syncthreads();
        s[tid] += t;
        __syncthreads();
    }
    if (i < N_NODES) {
        g_off[i] = s[tid] - v;     // exclusive local (padded)
        g_pos[i] = v;              // stash pdeg for scan_add's last element
        g_deg[i] = 0;              // restore zero invariant
    }
    if (tid == 1023) g_bsum[blockIdx.x] = s[1023];
}

__global__ void scan_add_kernel() {
    __shared__ int red[32];
    int tid  = threadIdx.x;
    int lane = tid & 31;
    int wid  = tid >> 5;
    int pre = 0;
    for (int t = tid; t < blockIdx.x; t += 1024) pre += g_bsum[t];
    #pragma unroll
    for (int d = 16; d; d >>= 1) pre += __shfl_down_sync(0xffffffffu, pre, d);
    if (lane == 0) red[wid] = pre;
    __syncthreads();
    if (wid == 0) {
        int v = red[lane];
        #pragma unroll
        for (int d = 16; d; d >>= 1) v += __shfl_down_sync(0xffffffffu, v, d);
        if (lane == 0) red[0] = v;
    }
    __syncthreads();
    int base = red[0];

    int i = blockIdx.x * 1024 + tid;
    if (i < N_NODES) {
        int o = g_off[i] + base;
        if (i == N_NODES - 1) g_off[N_NODES] = o + g_pos[i];  // padded total
        g_off[i] = o;
        g_pos[i] = o;
    }
}

__global__ void scatter_kernel(const int* __restrict__ src,
                               const int* __restrict__ dst,
                               const float* __restrict__ w) {
    int e = blockIdx.x * blockDim.x + threadIdx.x;
    if (e < N_EDGES) {
        int d = dst[e];
        int p = atomicAdd(&g_pos[d], 1);
        unsigned q = (unsigned)__float2int_rn(w[e] * WQ_SCALE);
        g_epk[p] = (q << 17) | (unsigned)src[e];
    }
}

__global__ void pad_fill_kernel() {
    int i = blockIdx.x * blockDim.x + threadIdx.x;
    if (i < N_NODES) {
        int p   = g_pos[i];        // = off + real_deg after scatter
        int end = g_off[i + 1];
        for (; p < end; p++) g_epk[p] = 0u;   // w=0, src=0 pad edges
    }
}

// ---------------- GEMM: C[n,64] = act(A[n,K] @ W[K,64] + b) ----------------
// Double-buffered staging: prefetch tile t+1 into registers while computing
// tile t from smem.
template <bool RELU, bool WRITE_HALF>
__global__ __launch_bounds__(256)
void gemm128_kernel(const float* __restrict__ A, const float* __restrict__ W,
                    const float* __restrict__ bias, float* __restrict__ C,
                    __half* __restrict__ Yh, int nrows, int K) {
    __shared__ __align__(16) u64 xs[2][128 * KK];
    __shared__ __align__(16) u64 ws[2][KK * 32];

    const int tid  = threadIdx.x;
    const int w    = tid >> 5;
    const int lane = tid & 31;
    const int rh   = lane >> 4;
    const int cg   = lane & 15;
    const int rbase = w * 16 + rh * 8;
    const int row0  = blockIdx.x * 128;

    const int xr[4] = { (tid) >> 3, (tid + 256) >> 3, (tid + 512) >> 3, (tid + 768) >> 3 };
    const int xk = tid & 7;
    const int wkk = tid >> 5;
    const int wp  = tid & 31;

    u64 acc[8][2];
    #pragma unroll
    for (int r = 0; r < 8; r++) { acc[r][0] = 0ull; acc[r][1] = 0ull; }

    const int ktiles = (K + KK - 1) / KK;

    float xv[4];
    float wv0, wv1;

    {
        #pragma unroll
        for (int j = 0; j < 4; j++) {
            int gr = row0 + xr[j];
            xv[j] = (gr < nrows && xk < K) ? __ldg(&A[(long)gr * K + xk]) : 0.f;
        }
        wv0 = (wkk < K) ? W[wkk * 64 + 2 * wp]     : 0.f;
        wv1 = (wkk < K) ? W[wkk * 64 + 2 * wp + 1] : 0.f;
    }
    #pragma unroll
    for (int j = 0; j < 4; j++) xs[0][xr[j] * KK + xk] = pack2(xv[j], xv[j]);
    ws[0][wkk * 32 + wp] = pack2(wv0, wv1);
    __syncthreads();

    for (int t = 0; t < ktiles; t++) {
        const int buf = t & 1;
        if (t + 1 < ktiles) {
            const int ko = (t + 1) * KK;
            #pragma unroll
            for (int j = 0; j < 4; j++) {
                int gr = row0 + xr[j];
                int gk = ko + xk;
                xv[j] = (gr < nrows && gk < K) ? __ldg(&A[(long)gr * K + gk]) : 0.f;
            }
            int gk = ko + wkk;
            wv0 = (gk < K) ? W[gk * 64 + 2 * wp]     : 0.f;
            wv1 = (gk < K) ? W[gk * 64 + 2 * wp + 1] : 0.f;
        }

        u64 wr[KK][2];
        #pragma unroll
        for (int kk = 0; kk < KK; kk++) {
            ulonglong2 wv = *(const ulonglong2*)&ws[buf][kk * 32 + 2 * cg];
            wr[kk][0] = wv.x; wr[kk][1] = wv.y;
        }
        #pragma unroll
        for (int kk2 = 0; kk2 < KK / 2; kk2++) {
            #pragma unroll
            for (int r = 0; r < 8; r++) {
                ulonglong2 xq = *(const ulonglong2*)&xs[buf][(rbase + r) * KK + 2 * kk2];
                FMA2(acc[r][0], xq.x, wr[2 * kk2][0]);
                FMA2(acc[r][1], xq.x, wr[2 * kk2][1]);
                FMA2(acc[r][0], xq.y, wr[2 * kk2 + 1][0]);
                FMA2(acc[r][1], xq.y, wr[2 * kk2 + 1][1]);
            }
        }

        if (t + 1 < ktiles) {
            #pragma unroll
            for (int j = 0; j < 4; j++) xs[buf ^ 1][xr[j] * KK + xk] = pack2(xv[j], xv[j]);
            ws[buf ^ 1][wkk * 32 + wp] = pack2(wv0, wv1);
            __syncthreads();
        }
    }

    float4 b4 = *(const float4*)&bias[4 * cg];
    #pragma unroll
    for (int r = 0; r < 8; r++) {
        int row = row0 + rbase + r;
        if (row < nrows) {
            float c0, c1, c2, c3;
            unpack2(c0, c1, acc[r][0]);
            unpack2(c2, c3, acc[r][1]);
            c0 += b4.x; c1 += b4.y; c2 += b4.z; c3 += b4.w;
            if (RELU) {
                c0 = fmaxf(c0, 0.f); c1 = fmaxf(c1, 0.f);
                c2 = fmaxf(c2, 0.f); c3 = fmaxf(c3, 0.f);
            }
            *(float4*)&C[(long)row * 64 + 4 * cg] = make_float4(c0, c1, c2, c3);
            if (WRITE_HALF) {
                long yi = (long)row * 64 + 4 * cg;
                __half2 p0 = __floats2half2_rn(c0, c1);
                __half2 p1 = __floats2half2_rn(c2, c3);
                uint2 pv; pv.x = *(unsigned*)&p0; pv.y = *(unsigned*)&p1;
                *(uint2*)&Yh[yi] = pv;
            }
        }
    }
}

// ---------------- APPNP propagation (uniform quarter-warp) ----------------
// Padded CSR (deg multiple of 8) => each quarter runs exactly 0 or 8 steps.
// One shfl(8, per-quarter mask) + one LDG.128 advances FOUR edges.
// CRITICAL: shfl mask must name ONLY this quarter's lanes — quarters diverge.
#define QSTEP(J) {                                                            \
    unsigned pj = __shfl_sync(qmask, pe, (J), 8);                             \
    float wj = (float)(pj >> 17) * WQ_INV;                                    \
    uint4 v = __ldg((const uint4*)(yin + ((long)(pj & 0x1FFFFu) << 6)) + ql); \
    float2 f0 = __half22float2(*(__half2*)&v.x);                              \
    float2 f1 = __half22float2(*(__half2*)&v.y);                              \
    float2 f2 = __half22float2(*(__half2*)&v.z);                              \
    float2 f3 = __half22float2(*(__half2*)&v.w);                              \
    acc0 = fmaf(wj, f0.x, acc0); acc1 = fmaf(wj, f0.y, acc1);                 \
    acc2 = fmaf(wj, f1.x, acc2); acc3 = fmaf(wj, f1.y, acc3);                 \
    acc4 = fmaf(wj, f2.x, acc4); acc5 = fmaf(wj, f2.y, acc5);                 \
    acc6 = fmaf(wj, f3.x, acc6); acc7 = fmaf(wj, f3.y, acc7); }

template <bool FINAL>
__global__ __launch_bounds__(256)
void prop_kernel(const __half* __restrict__ yin,
                 const uint4* __restrict__ hh, const float4* __restrict__ h4,
                 uint4* __restrict__ yout, float4* __restrict__ fout,
                 float c1, float c2) {
    int gtid = blockIdx.x * blockDim.x + threadIdx.x;
    int node = gtid >> 5;
    int lane = threadIdx.x & 31;
    if (node >= N_NODES) return;
    const int ql = lane & 7;
    const int q  = lane >> 3;
    const unsigned qmask = 0xFFu << (q * 8);      // this quarter's lanes only

    int beg = g_off[node];
    int end = g_off[node + 1];   // both multiples of 8

    float acc0 = 0.f, acc1 = 0.f, acc2 = 0.f, acc3 = 0.f;
    float acc4 = 0.f, acc5 = 0.f, acc6 = 0.f, acc7 = 0.f;

    for (int e = beg; e < end; e += 32) {
        int idx = e + lane;
        unsigned pe = (idx < end) ? __ldg(&g_epk[idx]) : 0u;
        int cnt = end - e;                 // multiple of 8
        if (q * 8 < cnt) {                 // quarter active => exactly 8 steps
            #pragma unroll
            for (int j = 0; j < 8; j++) QSTEP(j)
        }
    }

    #define XRED(A) A += __shfl_xor_sync(0xffffffffu, A, 8);  \
                    A += __shfl_xor_sync(0xffffffffu, A, 16);
    XRED(acc0) XRED(acc1) XRED(acc2) XRED(acc3)
    XRED(acc4) XRED(acc5) XRED(acc6) XRED(acc7)
    #undef XRED

    if (lane < 8) {
        long oi = (long)node * 8 + ql;
        if (FINAL) {
            float4 ha = h4[oi * 2];
            float4 hb = h4[oi * 2 + 1];
            fout[oi * 2]     = make_float4(fmaf(c1, acc0, c2 * ha.x),
                                           fmaf(c1, acc1, c2 * ha.y),
                                           fmaf(c1, acc2, c2 * ha.z),
                                           fmaf(c1, acc3, c2 * ha.w));
            fout[oi * 2 + 1] = make_float4(fmaf(c1, acc4, c2 * hb.x),
                                           fmaf(c1, acc5, c2 * hb.y),
                                           fmaf(c1, acc6, c2 * hb.z),
                                           fmaf(c1, acc7, c2 * hb.w));
        } else {
            uint4 hv = hh[oi];
            float2 g0 = __half22float2(*(__half2*)&hv.x);
            float2 g1 = __half22float2(*(__half2*)&hv.y);
            float2 g2 = __half22float2(*(__half2*)&hv.z);
            float2 g3 = __half22float2(*(__half2*)&hv.w);
            __half2 p0 = __floats2half2_rn(fmaf(c1, acc0, c2 * g0.x),
                                           fmaf(c1, acc1, c2 * g0.y));
            __half2 p1 = __floats2half2_rn(fmaf(c1, acc2, c2 * g1.x),
                                           fmaf(c1, acc3, c2 * g1.y));
            __half2 p2 = __floats2half2_rn(fmaf(c1, acc4, c2 * g2.x),
                                           fmaf(c1, acc5, c2 * g2.y));
            __half2 p3 = __floats2half2_rn(fmaf(c1, acc6, c2 * g3.x),
                                           fmaf(c1, acc7, c2 * g3.y));
            uint4 pv;
            pv.x = *(unsigned*)&p0; pv.y = *(unsigned*)&p1;
            pv.z = *(unsigned*)&p2; pv.w = *(unsigned*)&p3;
            yout[oi] = pv;
        }
    }
}

// ---------------- launch ----------------
extern "C" void kernel_launch(void* const* d_in, const int* in_sizes, int n_in,
                              void* d_out, int out_size) {
    const float* x    = (const float*)d_in[0];
    const int*   esrc = (const int*)d_in[1];
    const int*   edst = (const int*)d_in[2];
    const float* ew   = (const float*)d_in[3];
    const float* W1   = (const float*)d_in[4];
    const float* b1   = (const float*)d_in[5];
    const float* W2   = (const float*)d_in[6];
    const float* b2   = (const float*)d_in[7];
    float* out = (float*)d_out;

    static cudaStream_t s_side = nullptr;
    static cudaEvent_t  s_evFork = nullptr, s_evJoin = nullptr;
    if (!s_side) {
        cudaStreamCreateWithFlags(&s_side, cudaStreamNonBlocking);
        cudaEventCreateWithFlags(&s_evFork, cudaEventDisableTiming);
        cudaEventCreateWithFlags(&s_evJoin, cudaEventDisableTiming);
    }

    float  *h1_p, *h_p;
    __half *hh_p, *ya_p, *yb_p;
    cudaGetSymbolAddress((void**)&h1_p, g_h1);
    cudaGetSymbolAddress((void**)&h_p,  g_h);
    cudaGetSymbolAddress((void**)&hh_p, g_hh);
    cudaGetSymbolAddress((void**)&ya_p, g_ya);
    cudaGetSymbolAddress((void**)&yb_p, g_yb);

    // --- fork: CSR build on side stream, concurrent with MLP GEMMs ---
    cudaEventRecord(s_evFork, 0);
    cudaStreamWaitEvent(s_side, s_evFork, 0);
    hist_kernel<<<(N_EDGES / 4 + 255) / 256, 256, 0, s_side>>>(edst);
    scan_local_kernel<<<NSCAN_BLOCKS, 1024, 0, s_side>>>();
    scan_add_kernel<<<NSCAN_BLOCKS, 1024, 0, s_side>>>();
    scatter_kernel<<<(N_EDGES + 255) / 256, 256, 0, s_side>>>(esrc, edst, ew);
    pad_fill_kernel<<<(N_NODES + 255) / 256, 256, 0, s_side>>>();
    cudaEventRecord(s_evJoin, s_side);

    // --- MLP encoder on main stream (GEMM2 also emits y_0 = fp16(h)) ---
    int gblocks = (N_NODES + 127) / 128;
    gemm128_kernel<true,  false><<<gblocks, 256>>>(x,    W1, b1, h1_p, nullptr, N_NODES, IN_F);
    gemm128_kernel<false, true ><<<gblocks, 256>>>(h1_p, W2, b2, h_p,  hh_p,    N_NODES, HID);

    // --- join, then K propagation steps ---
    cudaStreamWaitEvent(0, s_evJoin, 0);

    int pblocks = (N_NODES * 32 + 255) / 256;
    const __half* yin = hh_p;                 // y_0 = fp16(h)
    __half* ybufs[2] = { ya_p, yb_p };
    for (int k = 0; k < K_ITERS; k++) {
        if (k < K_ITERS - 1) {
            float c1 = (float)(0.9 * SCALE_S);
            float c2 = (float)(0.1 * pow(SCALE_S, (double)(k + 1)));
            __half* yo = ybufs[k & 1];
            prop_kernel<false><<<pblocks, 256>>>(yin, (const uint4*)hh_p, nullptr,
                                                 (uint4*)yo, nullptr, c1, c2);
            yin = yo;
        } else {
            float c1 = (float)(0.9 * pow(1.0 / SCALE_S, (double)(K_ITERS - 1)));
            float c2 = 0.1f;
            prop_kernel<true><<<pblocks, 256>>>(yin, nullptr, (const float4*)h_p,
                                                nullptr, (float4*)out, c1, c2);
        }
    }
}

// round 11
// speedup vs baseline: 1.1373x; 1.1373x over previous
#include <cuda_runtime.h>
#include <cuda_bf16.h>
#include <cuda_fp16.h>
#include <math.h>

// ---------------- problem constants ----------------
#define N_NODES 100000
#define N_EDGES 3200000
#define IN_F    500
#define HID     64
#define OUT_F   64
#define ALPHA   0.1f
#define K_ITERS 10

#define NSCAN_BLOCKS ((N_NODES + 1023) / 1024)   // 98
#define KK 8                                      // gemm k-tile
#define SCALE_S 0.0625                            // 1/16 per-iteration z scaling
#define WQ_SCALE 32767.0f
#define WQ_INV   (1.0f / 32767.0f)

typedef unsigned long long u64;

// ---------------- static device scratch ----------------
__device__ float    g_h1[N_NODES * HID];          // relu(x@W1+b1)
__device__ float    g_h [N_NODES * OUT_F];        // fp32 h (final iter)
__device__ __half   g_hh[N_NODES * OUT_F];        // fp16 h (= y_0, alpha term)
__device__ __half   g_ya[N_NODES * OUT_F];        // fp16 iterate ping
__device__ __half   g_yb[N_NODES * OUT_F];        // fp16 iterate pong
__device__ int      g_deg[N_NODES];               // ALWAYS zero at launch entry
__device__ int      g_off[N_NODES + 1];
__device__ int      g_pos[N_NODES];
__device__ unsigned g_epk[N_EDGES];               // packed edge: w15 | src17
__device__ int      g_bsum[NSCAN_BLOCKS];

// ---------------- f32x2 helpers ----------------
__device__ __forceinline__ u64 pack2(float x, float y) {
    u64 r; asm("mov.b64 %0, {%1, %2};" : "=l"(r) : "f"(x), "f"(y)); return r;
}
__device__ __forceinline__ void unpack2(float& x, float& y, u64 v) {
    asm("mov.b64 {%0, %1}, %2;" : "=f"(x), "=f"(y) : "l"(v));
}
#define FMA2(acc, a, b) asm("fma.rn.f32x2 %0, %1, %2, %0;" : "+l"(acc) : "l"(a), "l"(b))

// ---------------- CSR construction (4 kernels) ----------------
__global__ void hist_kernel(const int* __restrict__ dst) {
    int i = blockIdx.x * blockDim.x + threadIdx.x;
    if (i * 4 + 3 < N_EDGES) {
        int4 d = ((const int4*)dst)[i];
        atomicAdd(&g_deg[d.x], 1);
        atomicAdd(&g_deg[d.y], 1);
        atomicAdd(&g_deg[d.z], 1);
        atomicAdd(&g_deg[d.w], 1);
    } else {
        for (int e = i * 4; e < N_EDGES; e++) atomicAdd(&g_deg[dst[e]], 1);
    }
}

__global__ void scan_local_kernel() {
    __shared__ int s[1024];
    int tid = threadIdx.x;
    int i = blockIdx.x * 1024 + tid;
    int v = (i < N_NODES) ? g_deg[i] : 0;
    s[tid] = v;
    __syncthreads();
    #pragma unroll
    for (int d = 1; d < 1024; d <<= 1) {
        int t = (tid >= d) ? s[tid - d] : 0;
        __syncthreads();
        s[tid] += t;
        __syncthreads();
    }
    if (i < N_NODES) {
        g_off[i] = s[tid] - v;     // exclusive local
        g_deg[i] = 0;              // restore zero invariant for next launch
    }
    if (tid == 1023) g_bsum[blockIdx.x] = s[1023];
}

__global__ void scan_add_kernel() {
    __shared__ int red[32];
    int tid  = threadIdx.x;
    int lane = tid & 31;
    int wid  = tid >> 5;
    int pre = 0;
    for (int t = tid; t < blockIdx.x; t += 1024) pre += g_bsum[t];
    #pragma unroll
    for (int d = 16; d; d >>= 1) pre += __shfl_down_sync(0xffffffffu, pre, d);
    if (lane == 0) red[wid] = pre;
    __syncthreads();
    if (wid == 0) {
        int v = red[lane];
        #pragma unroll
        for (int d = 16; d; d >>= 1) v += __shfl_down_sync(0xffffffffu, v, d);
        if (lane == 0) red[0] = v;
    }
    __syncthreads();
    int base = red[0];

    int i = blockIdx.x * 1024 + tid;
    if (i < N_NODES) {
        int o = g_off[i] + base;
        g_off[i] = o;
        g_pos[i] = o;
    }
    if (blockIdx.x == 0 && tid == 0) g_off[N_NODES] = N_EDGES;
}

__global__ void scatter_kernel(const int* __restrict__ src,
                               const int* __restrict__ dst,
                               const float* __restrict__ w) {
    int e = blockIdx.x * blockDim.x + threadIdx.x;
    if (e < N_EDGES) {
        int d = dst[e];
        int p = atomicAdd(&g_pos[d], 1);
        unsigned q = (unsigned)__float2int_rn(w[e] * WQ_SCALE);
        g_epk[p] = (q << 17) | (unsigned)src[e];
    }
}

// ---------------- GEMM: C[n,64] = act(A[n,K] @ W[K,64] + b) ----------------
// Double-buffered staging: prefetch tile t+1 into registers while computing
// tile t from smem; STS into the opposite buffer; one sync per tile.
template <bool RELU, bool WRITE_HALF>
__global__ __launch_bounds__(256)
void gemm128_kernel(const float* __restrict__ A, const float* __restrict__ W,
                    const float* __restrict__ bias, float* __restrict__ C,
                    __half* __restrict__ Yh, int nrows, int K) {
    __shared__ __align__(16) u64 xs[2][128 * KK];
    __shared__ __align__(16) u64 ws[2][KK * 32];

    const int tid  = threadIdx.x;
    const int w    = tid >> 5;
    const int lane = tid & 31;
    const int rh   = lane >> 4;
    const int cg   = lane & 15;
    const int rbase = w * 16 + rh * 8;
    const int row0  = blockIdx.x * 128;

    const int xr[4] = { (tid) >> 3, (tid + 256) >> 3, (tid + 512) >> 3, (tid + 768) >> 3 };
    const int xk = tid & 7;
    const int wkk = tid >> 5;
    const int wp  = tid & 31;

    u64 acc[8][2];
    #pragma unroll
    for (int r = 0; r < 8; r++) { acc[r][0] = 0ull; acc[r][1] = 0ull; }

    const int ktiles = (K + KK - 1) / KK;

    float xv[4];
    float wv0, wv1;

    {
        #pragma unroll
        for (int j = 0; j < 4; j++) {
            int gr = row0 + xr[j];
            xv[j] = (gr < nrows && xk < K) ? __ldg(&A[(long)gr * K + xk]) : 0.f;
        }
        wv0 = (wkk < K) ? W[wkk * 64 + 2 * wp]     : 0.f;
        wv1 = (wkk < K) ? W[wkk * 64 + 2 * wp + 1] : 0.f;
    }
    #pragma unroll
    for (int j = 0; j < 4; j++) xs[0][xr[j] * KK + xk] = pack2(xv[j], xv[j]);
    ws[0][wkk * 32 + wp] = pack2(wv0, wv1);
    __syncthreads();

    for (int t = 0; t < ktiles; t++) {
        const int buf = t & 1;
        if (t + 1 < ktiles) {
            const int ko = (t + 1) * KK;
            #pragma unroll
            for (int j = 0; j < 4; j++) {
                int gr = row0 + xr[j];
                int gk = ko + xk;
                xv[j] = (gr < nrows && gk < K) ? __ldg(&A[(long)gr * K + gk]) : 0.f;
            }
            int gk = ko + wkk;
            wv0 = (gk < K) ? W[gk * 64 + 2 * wp]     : 0.f;
            wv1 = (gk < K) ? W[gk * 64 + 2 * wp + 1] : 0.f;
        }

        u64 wr[KK][2];
        #pragma unroll
        for (int kk = 0; kk < KK; kk++) {
            ulonglong2 wv = *(const ulonglong2*)&ws[buf][kk * 32 + 2 * cg];
            wr[kk][0] = wv.x; wr[kk][1] = wv.y;
        }
        #pragma unroll
        for (int kk2 = 0; kk2 < KK / 2; kk2++) {
            #pragma unroll
            for (int r = 0; r < 8; r++) {
                ulonglong2 xq = *(const ulonglong2*)&xs[buf][(rbase + r) * KK + 2 * kk2];
                FMA2(acc[r][0], xq.x, wr[2 * kk2][0]);
                FMA2(acc[r][1], xq.x, wr[2 * kk2][1]);
                FMA2(acc[r][0], xq.y, wr[2 * kk2 + 1][0]);
                FMA2(acc[r][1], xq.y, wr[2 * kk2 + 1][1]);
            }
        }

        if (t + 1 < ktiles) {
            #pragma unroll
            for (int j = 0; j < 4; j++) xs[buf ^ 1][xr[j] * KK + xk] = pack2(xv[j], xv[j]);
            ws[buf ^ 1][wkk * 32 + wp] = pack2(wv0, wv1);
            __syncthreads();
        }
    }

    float4 b4 = *(const float4*)&bias[4 * cg];
    #pragma unroll
    for (int r = 0; r < 8; r++) {
        int row = row0 + rbase + r;
        if (row < nrows) {
            float c0, c1, c2, c3;
            unpack2(c0, c1, acc[r][0]);
            unpack2(c2, c3, acc[r][1]);
            c0 += b4.x; c1 += b4.y; c2 += b4.z; c3 += b4.w;
            if (RELU) {
                c0 = fmaxf(c0, 0.f); c1 = fmaxf(c1, 0.f);
                c2 = fmaxf(c2, 0.f); c3 = fmaxf(c3, 0.f);
            }
            *(float4*)&C[(long)row * 64 + 4 * cg] = make_float4(c0, c1, c2, c3);
            if (WRITE_HALF) {
                long yi = (long)row * 64 + 4 * cg;
                __half2 p0 = __floats2half2_rn(c0, c1);
                __half2 p1 = __floats2half2_rn(c2, c3);
                uint2 pv; pv.x = *(unsigned*)&p0; pv.y = *(unsigned*)&p1;
                *(uint2*)&Yh[yi] = pv;
            }
        }
    }
}

// ---------------- APPNP propagation (half-warp per edge, balanced tail) ----
// Lanes 0-15 / 16-31 process different edges: one shfl + one LDG.64 advances
// TWO edges. Full batches: fixed 16/16 split (unrolled). Tail batch: BALANCED
// split jcnt=(cnt+1)/2 per half via width-32 per-lane-source shfl — halves
// stay converged and no half runs useless w=0 steps.
#define PAIR_BODY(PJ) {                                                       \
    float wj = (float)((PJ) >> 17) * WQ_INV;                                  \
    uint2 v = *(const uint2*)(yin + ((long)((PJ) & 0x1FFFFu) << 6) + (hl << 2)); \
    float2 f0 = __half22float2(*(__half2*)&v.x);                              \
    float2 f1 = __half22float2(*(__half2*)&v.y);                              \
    a0 = fmaf(wj, f0.x, a0); a1 = fmaf(wj, f0.y, a1);                         \
    a2 = fmaf(wj, f1.x, a2); a3 = fmaf(wj, f1.y, a3); }

template <bool FINAL>
__global__ __launch_bounds__(256)
void prop_kernel(const __half* __restrict__ yin,
                 const uint2* __restrict__ hh, const float4* __restrict__ h4,
                 uint2* __restrict__ yout, float4* __restrict__ fout,
                 float c1, float c2) {
    int gtid = blockIdx.x * blockDim.x + threadIdx.x;
    int node = gtid >> 5;
    int lane = threadIdx.x & 31;
    if (node >= N_NODES) return;
    const int hl = lane & 15;

    int beg = g_off[node];
    int end = g_off[node + 1];

    float a0 = 0.f, a1 = 0.f, a2 = 0.f, a3 = 0.f;
    int e = beg;
    // full 32-edge batches: fixed 16/16 split, fully unrolled
    for (; e + 32 <= end; e += 32) {
        unsigned pe = __ldg(&g_epk[e + lane]);
        #pragma unroll
        for (int j = 0; j < 16; j++) {
            unsigned pj = __shfl_sync(0xffffffffu, pe, j, 16);
            PAIR_BODY(pj)
        }
    }
    // tail batch: balanced split — half A edges [e, e+jcnt), half B [e+jcnt, e+cnt)
    if (e < end) {
        int idx = e + lane;
        unsigned pe = (idx < end) ? __ldg(&g_epk[idx]) : 0u;
        int cnt  = end - e;                 // 1..31
        int jcnt = (cnt + 1) >> 1;
        int hoff = (lane & 16) ? jcnt : 0;  // half B sources from lane j+jcnt
        for (int j = 0; j < jcnt; j++) {
            unsigned pj = __shfl_sync(0xffffffffu, pe, j + hoff, 32);
            PAIR_BODY(pj)                   // odd cnt: half B's last pj==0 (w=0)
        }
    }
    a0 += __shfl_xor_sync(0xffffffffu, a0, 16);
    a1 += __shfl_xor_sync(0xffffffffu, a1, 16);
    a2 += __shfl_xor_sync(0xffffffffu, a2, 16);
    a3 += __shfl_xor_sync(0xffffffffu, a3, 16);

    if (lane < 16) {
        long oi = (long)node * 16 + hl;
        if (FINAL) {
            float4 hv = h4[oi];
            fout[oi] = make_float4(fmaf(c1, a0, c2 * hv.x),
                                   fmaf(c1, a1, c2 * hv.y),
                                   fmaf(c1, a2, c2 * hv.z),
                                   fmaf(c1, a3, c2 * hv.w));
        } else {
            uint2 hv2 = hh[oi];
            float2 f0 = __half22float2(*(__half2*)&hv2.x);
            float2 f1 = __half22float2(*(__half2*)&hv2.y);
            __half2 p0 = __floats2half2_rn(fmaf(c1, a0, c2 * f0.x),
                                           fmaf(c1, a1, c2 * f0.y));
            __half2 p1 = __floats2half2_rn(fmaf(c1, a2, c2 * f1.x),
                                           fmaf(c1, a3, c2 * f1.y));
            uint2 pv; pv.x = *(unsigned*)&p0; pv.y = *(unsigned*)&p1;
            yout[oi] = pv;
        }
    }
}

// ---------------- launch ----------------
extern "C" void kernel_launch(void* const* d_in, const int* in_sizes, int n_in,
                              void* d_out, int out_size) {
    const float* x    = (const float*)d_in[0];
    const int*   esrc = (const int*)d_in[1];
    const int*   edst = (const int*)d_in[2];
    const float* ew   = (const float*)d_in[3];
    const float* W1   = (const float*)d_in[4];
    const float* b1   = (const float*)d_in[5];
    const float* W2   = (const float*)d_in[6];
    const float* b2   = (const float*)d_in[7];
    float* out = (float*)d_out;

    static cudaStream_t s_side = nullptr;
    static cudaEvent_t  s_evFork = nullptr, s_evJoin = nullptr;
    if (!s_side) {
        cudaStreamCreateWithFlags(&s_side, cudaStreamNonBlocking);
        cudaEventCreateWithFlags(&s_evFork, cudaEventDisableTiming);
        cudaEventCreateWithFlags(&s_evJoin, cudaEventDisableTiming);
    }

    float  *h1_p, *h_p;
    __half *hh_p, *ya_p, *yb_p;
    cudaGetSymbolAddress((void**)&h1_p, g_h1);
    cudaGetSymbolAddress((void**)&h_p,  g_h);
    cudaGetSymbolAddress((void**)&hh_p, g_hh);
    cudaGetSymbolAddress((void**)&ya_p, g_ya);
    cudaGetSymbolAddress((void**)&yb_p, g_yb);

    // --- fork: CSR build on side stream, concurrent with MLP GEMMs ---
    cudaEventRecord(s_evFork, 0);
    cudaStreamWaitEvent(s_side, s_evFork, 0);
    hist_kernel<<<(N_EDGES / 4 + 255) / 256, 256, 0, s_side>>>(edst);
    scan_local_kernel<<<NSCAN_BLOCKS, 1024, 0, s_side>>>();
    scan_add_kernel<<<NSCAN_BLOCKS, 1024, 0, s_side>>>();
    scatter_kernel<<<(N_EDGES + 255) / 256, 256, 0, s_side>>>(esrc, edst, ew);
    cudaEventRecord(s_evJoin, s_side);

    // --- MLP encoder on main stream (GEMM2 also emits y_0 = fp16(h)) ---
    int gblocks = (N_NODES + 127) / 128;
    gemm128_kernel<true,  false><<<gblocks, 256>>>(x,    W1, b1, h1_p, nullptr, N_NODES, IN_F);
    gemm128_kernel<false, true ><<<gblocks, 256>>>(h1_p, W2, b2, h_p,  hh_p,    N_NODES, HID);

    // --- join, then K propagation steps ---
    cudaStreamWaitEvent(0, s_evJoin, 0);

    int pblocks = (N_NODES * 32 + 255) / 256;
    const __half* yin = hh_p;                 // y_0 = fp16(h)
    __half* ybufs[2] = { ya_p, yb_p };
    for (int k = 0; k < K_ITERS; k++) {
        if (k < K_ITERS - 1) {
            float c1 = (float)(0.9 * SCALE_S);
            float c2 = (float)(0.1 * pow(SCALE_S, (double)(k + 1)));
            __half* yo = ybufs[k & 1];
            prop_kernel<false><<<pblocks, 256>>>(yin, (const uint2*)hh_p, nullptr,
                                                 (uint2*)yo, nullptr, c1, c2);
            yin = yo;
        } else {
            float c1 = (float)(0.9 * pow(1.0 / SCALE_S, (double)(K_ITERS - 1)));
            float c2 = 0.1f;
            prop_kernel<true><<<pblocks, 256>>>(yin, nullptr, (const float4*)h_p,
                                                nullptr, (float4*)out, c1, c2);
        }
    }
}